// round 8
// baseline (speedup 1.0000x reference)
#include <cuda_runtime.h>
#include <stdint.h>

// SparseGather: out[m, i, j, c] = inputs[n_m, y0_m + i, x0_m + j, c]
// inputs: (N=4, H=512, W=512, C=64) fp32
// active_block_indices: (M=4096, 3) int32 -> (n, by, bx); y0 = by*16, x0 = bx*16
// out: (M, 16, 16, 64) fp32
//
// Units of 32B chunks (ulonglong4; C=64 fp32 -> 8 chunks per pixel):
//   CU   = 8                     (chunks per pixel)
//   WCU  = 512 * 8 = 4096        (row stride, chunks)
//   HWCU = 512 * WCU             (image stride, chunks)
// One input block row: 16 px * 8 = 128 contiguous chunks (4 KB).
// One output block: 16*128 = 2048 contiguous chunks (64 KB).
//
// R8: 4 rows/CTA (granularity optimum from R1..R6 sweep), 256-bit accesses.
//   thread t -> chunk (t&127) of rows (t>>7) and (t>>7)+2:
//     2x ld.global.nc.L2::evict_last.v4.b64 (input retention priority in L2,
//        maximizes duplicate-block dedup; 170MB unique footprint vs 126MB L2)
//     2x st.global.cs.v4.b64 (evict-first streaming store; write-once data)
//   Half the LDG/STG instruction count of R5.

#define CU   8
#define WCU  (512 * CU)
#define HWCU (512 * WCU)

__device__ __forceinline__ ulonglong4 ldg256_evict_last(const ulonglong4* p)
{
    ulonglong4 v;
    asm volatile("ld.global.nc.L2::evict_last.v4.b64 {%0,%1,%2,%3}, [%4];"
                 : "=l"(v.x), "=l"(v.y), "=l"(v.z), "=l"(v.w)
                 : "l"(p));
    return v;
}

__device__ __forceinline__ void stg256_cs(ulonglong4* p, ulonglong4 v)
{
    asm volatile("st.global.cs.v4.b64 [%0], {%1,%2,%3,%4};"
                 :: "l"(p), "l"(v.x), "l"(v.y), "l"(v.z), "l"(v.w)
                 : "memory");
}

__global__ __launch_bounds__(256) void sparse_gather_kernel(
    const ulonglong4* __restrict__ in,
    const int*        __restrict__ idx,
    ulonglong4*       __restrict__ out)
{
    const int b  = blockIdx.x;        // 0 .. 4*M-1
    const int m  = b >> 2;            // block index
    const int r0 = (b & 3) << 2;      // row offset: 0, 4, 8, 12
    const int t  = threadIdx.x;       // 0..255

    const int rA = (t >> 7);          // 0 or 1: first row this thread handles
    const int c  = (t & 127);         // chunk within row

    const int n  = idx[3 * m + 0];
    const int by = idx[3 * m + 1];
    const int bx = idx[3 * m + 2];

    const ulonglong4* src = in
        + (size_t)n * HWCU
        + (size_t)(by * 16 + r0) * WCU
        + (size_t)(bx * 16) * CU;

    ulonglong4* dst = out + (size_t)m * 2048 + (size_t)r0 * 128;

    // rows rA and rA+2 of this quarter-block; each row = 128 contiguous chunks.
    ulonglong4 v0 = ldg256_evict_last(&src[(size_t)rA * WCU + c]);
    ulonglong4 v1 = ldg256_evict_last(&src[(size_t)(rA + 2) * WCU + c]);
    stg256_cs(&dst[rA * 128 + c],       v0);
    stg256_cs(&dst[(rA + 2) * 128 + c], v1);
}

extern "C" void kernel_launch(void* const* d_in, const int* in_sizes, int n_in,
                              void* d_out, int out_size)
{
    const ulonglong4* in  = (const ulonglong4*)d_in[0];
    const int*        idx = (const int*)d_in[2];   // active_block_indices
    ulonglong4*       out = (ulonglong4*)d_out;

    const int M = in_sizes[2] / 3;                 // 4096

    sparse_gather_kernel<<<4 * M, 256>>>(in, idx, out);
}